// round 16
// baseline (speedup 1.0000x reference)
#include <cuda_runtime.h>
#include <cuda_fp16.h>
#include <math.h>
#include <stdint.h>

#define B_    8
#define T_    8
#define C_    256
#define CH_   64
#define Wd    56
#define HW_   3136
#define PT    128
#define NPB   25          // expand px-blocks / v-partial slots
#define PXT   16          // px per block in k_reduce

typedef unsigned long long ull;

// ---------------- scratch (device globals) ----------------
__device__ float g_maxavg[(size_t)B_ * T_ * 2 * HW_];
__device__ float g_gate[(size_t)B_ * T_ * HW_];
__device__ __align__(16) float g_wrf[C_ * 3 * CH_];     // [c*192 + dt*64 + ch]
__device__ __align__(16) float g_we[CH_ * C_];          // [cin*256 + cout]
__device__ __align__(16) __half2 g_th[(size_t)B_ * CH_ * T_ * HW_ / 2];   // fp16 t-buffer
__device__ __align__(16) __half2 g_xsh[(size_t)B_ * T_ * C_ * HW_ / 2];   // fp16 x_s = x*gate
__device__ __align__(16) __half2 g_xth[(size_t)B_ * C_ * T_ * HW_ / 2];   // fp16 x_t
__device__ float g_vpart[(size_t)B_ * C_ * T_ * NPB];
__device__ float g_kern[B_ * C_ * 3];

// ---------------- helpers ----------------
__device__ __forceinline__ void ffma2(ull& d, ull a, ull b) {
    asm("fma.rn.f32x2 %0, %1, %2, %0;" : "+l"(d) : "l"(a), "l"(b));
}
__device__ __forceinline__ ull packdup(float w) {
    ull u; asm("mov.b64 %0, {%1, %1};" : "=l"(u) : "f"(w)); return u;
}
__device__ __forceinline__ float2 unpk(ull u) {
    float2 f; asm("mov.b64 {%0, %1}, %2;" : "=f"(f.x), "=f"(f.y) : "l"(u)); return f;
}
__device__ __forceinline__ unsigned sptr(const void* p) {
    return (unsigned)__cvta_generic_to_shared(p);
}
__device__ __forceinline__ void cpasync16(unsigned dst, const void* src) {
    asm volatile("cp.async.ca.shared.global [%0], [%1], 16;" :: "r"(dst), "l"(src));
}
__device__ __forceinline__ void cp_commit() { asm volatile("cp.async.commit_group;"); }
__device__ __forceinline__ void cp_wait0()  { asm volatile("cp.async.wait_group 0;"); }

// ---------------- prep: weight transposes ----------------
__global__ void k_prep(const float* __restrict__ wr, const float* __restrict__ we) {
    int idx = blockIdx.x * blockDim.x + threadIdx.x;
    if (idx < C_ * 3 * CH_) {
        int c = idx / 192;
        int r = idx % 192;
        int dt = r / 64, ch = r % 64;
        g_wrf[idx] = wr[ch * (C_ * 3) + c * 3 + dt];
    }
    if (idx < CH_ * C_) {
        int cout = idx & 255, cin = idx >> 8;
        g_we[idx] = we[cout * CH_ + cin];
    }
}

// ---------------- channel max/mean (float4) ----------------
__global__ __launch_bounds__(256) void k_maxmean(const float* __restrict__ x) {
    int bt = blockIdx.y;
    int p4 = blockIdx.x * blockDim.x + threadIdx.x;
    if (p4 >= HW_ / 4) return;
    const float4* xp = (const float4*)(x + (size_t)bt * C_ * HW_) + p4;
    float4 mx = xp[0];
    float4 sm = mx;
#pragma unroll 8
    for (int c = 1; c < C_; c++) {
        float4 v = xp[(size_t)c * (HW_ / 4)];
        mx.x = fmaxf(mx.x, v.x); mx.y = fmaxf(mx.y, v.y);
        mx.z = fmaxf(mx.z, v.z); mx.w = fmaxf(mx.w, v.w);
        sm.x += v.x; sm.y += v.y; sm.z += v.z; sm.w += v.w;
    }
    float4* mo = (float4*)(g_maxavg + (size_t)bt * 2 * HW_);
    mo[p4] = mx;
    sm.x *= (1.f / C_); sm.y *= (1.f / C_); sm.z *= (1.f / C_); sm.w *= (1.f / C_);
    mo[HW_ / 4 + p4] = sm;
}

// ---------------- 7x7 conv -> spatial gate ----------------
__global__ __launch_bounds__(256) void k_spatial(const float* __restrict__ w) {
    __shared__ float sw[98];
    int tid = threadIdx.x;
    if (tid < 98) sw[tid] = w[tid];
    __syncthreads();
    int bt = blockIdx.y;
    int p = blockIdx.x * blockDim.x + tid;
    if (p >= HW_) return;
    int py = p / Wd, px = p % Wd;
    const float* mb = g_maxavg + (size_t)bt * 2 * HW_;
    float s = 0.f;
#pragma unroll
    for (int ky = 0; ky < 7; ky++) {
        int iy = py + ky - 3;
        if (iy < 0 || iy >= Wd) continue;
#pragma unroll
        for (int kx = 0; kx < 7; kx++) {
            int ix = px + kx - 3;
            if (ix < 0 || ix >= Wd) continue;
            float m = mb[iy * Wd + ix];
            float a = mb[HW_ + iy * Wd + ix];
            s += sw[ky * 7 + kx] * m + sw[49 + ky * 7 + kx] * a;
        }
    }
    g_gate[(size_t)bt * HW_ + p] = 1.f + 1.f / (1.f + __expf(-s));
}

// ---------------- t-batched gated reduce conv3d + BN + relu (R13 body + cheap x_s export) ----------------
__global__ __launch_bounds__(128) void k_reduce(
    const float* __restrict__ x, const float* __restrict__ gamma,
    const float* __restrict__ beta, const float* __restrict__ mean,
    const float* __restrict__ var) {
    __shared__ float sinv[64], sbias[64];
    __shared__ __align__(16) ull sg[8][8];
    __shared__ __align__(16) ull sxs[8][8][10];
    __shared__ __align__(16) float swf[2][1536];

    int tid = threadIdx.x;
    int warp = tid >> 5, lane = tid & 31;
    int chg = lane & 15, pxg = lane >> 4;
    int pair = warp * 2 + pxg;
    int p0 = blockIdx.x * PXT;
    int b = blockIdx.y;

    if (tid < 64) {
        float iv = gamma[tid] * rsqrtf(var[tid] + 1e-5f);
        sinv[tid] = iv;
        sbias[tid] = beta[tid] - mean[tid] * iv;
        int tin = tid >> 3, pr = tid & 7;
        float2 g = *(const float2*)(g_gate + (size_t)(b * T_ + tin) * HW_ + p0 + pr * 2);
        sg[tin][pr] = *(ull*)&g;
    }
    {
        int c = tid >> 3, pr = tid & 7;
        if (c < 8) {
            sxs[c][pr][0] = 0ULL;
            sxs[c][pr][9] = 0ULL;
        }
    }
    __syncthreads();

    int sc = tid >> 4, sp = tid & 7, shalf = (tid >> 3) & 1;
    const float* xb = x + ((size_t)b * T_ * C_) * HW_ + p0 + sp * 2;
    float2 sgate[4];
#pragma unroll
    for (int k = 0; k < 4; k++) {
        ull g = sg[shalf * 4 + k][sp];
        sgate[k] = unpk(g);
    }

    // precomputed export pointers (half2 units); advance by 8*HW halves = 4*HW half2 per chunk
    __half2* xsh_p[4];
#pragma unroll
    for (int k = 0; k < 4; k++) {
        int tin = shalf * 4 + k;
        xsh_p[k] = g_xsh + (((size_t)(b * T_ + tin) * C_ + sc) * HW_ + p0 + sp * 2) / 2;
    }

    unsigned swf_s = sptr(&swf[0][0]);

#pragma unroll
    for (int k = 0; k < 3; k++) {
        int q = tid + k * 128;
        cpasync16(swf_s + q * 16, g_wrf + q * 4);
    }
    cp_commit();
    float2 xf[4];
#pragma unroll
    for (int k = 0; k < 4; k++) {
        int tin = shalf * 4 + k;
        xf[k] = *(const float2*)(xb + ((size_t)(tin * C_ + sc)) * HW_);
    }

    ull acc[4][8];
#pragma unroll
    for (int i = 0; i < 4; i++)
#pragma unroll
        for (int t = 0; t < 8; t++) acc[i][t] = 0ULL;

    for (int c0 = 0; c0 < C_; c0 += 8) {
        int buf = (c0 >> 3) & 1;
        __syncthreads();
#pragma unroll
        for (int k = 0; k < 4; k++) {
            int tin = shalf * 4 + k;
            float2 v;
            v.x = xf[k].x * sgate[k].x;
            v.y = xf[k].y * sgate[k].y;
            sxs[sc][sp][1 + tin] = *(ull*)&v;
            *xsh_p[k] = __floats2half2_rn(v.x, v.y);   // pointer-based, no index math
            xsh_p[k] += 4 * HW_;                       // c += 8
        }
        cp_wait0();
        __syncthreads();

        if (c0 + 8 < C_) {
#pragma unroll
            for (int k = 0; k < 3; k++) {
                int q = tid + k * 128;
                cpasync16(swf_s + (buf ^ 1) * 6144 + q * 16,
                          g_wrf + (c0 + 8) * 192 + q * 4);
            }
            cp_commit();
#pragma unroll
            for (int k = 0; k < 4; k++) {
                int tin = shalf * 4 + k;
                xf[k] = *(const float2*)(xb + ((size_t)(tin * C_ + c0 + 8 + sc)) * HW_);
            }
        }

#pragma unroll 2
        for (int cc = 0; cc < 8; cc++) {
            const ulonglong2* xp2 = (const ulonglong2*)&sxs[cc][pair][0];
            ulonglong2 a0 = xp2[0], a1 = xp2[1], a2 = xp2[2], a3 = xp2[3], a4 = xp2[4];
            ull xv[10] = {a0.x, a0.y, a1.x, a1.y, a2.x, a2.y, a3.x, a3.y, a4.x, a4.y};
#pragma unroll
            for (int dt = 0; dt < 3; dt++) {
                float4 wq = *(const float4*)&swf[buf][cc * 192 + dt * 64 + chg * 4];
                ull w0 = packdup(wq.x), w1 = packdup(wq.y);
                ull w2 = packdup(wq.z), w3 = packdup(wq.w);
#pragma unroll
                for (int t = 0; t < 8; t++) {
                    ffma2(acc[0][t], w0, xv[t + dt]);
                    ffma2(acc[1][t], w1, xv[t + dt]);
                    ffma2(acc[2][t], w2, xv[t + dt]);
                    ffma2(acc[3][t], w3, xv[t + dt]);
                }
            }
        }
    }

    int px = p0 + pair * 2;
#pragma unroll
    for (int i = 0; i < 4; i++) {
        int ch = chg * 4 + i;
        float inv = sinv[ch], bia = sbias[ch];
        __half2* dst = g_th + ((((size_t)(b * CH_ + ch)) * T_) * HW_ + px) / 2;
#pragma unroll
        for (int t = 0; t < 8; t++) {
            float2 f = unpk(acc[i][t]);
            float ox = fmaxf(fmaf(f.x, inv, bia), 0.f);
            float oy = fmaxf(fmaf(f.y, inv, bia), 0.f);
            dst[(size_t)t * (HW_ / 2)] = __floats2half2_rn(ox, oy);
        }
    }
}

// ---------------- expand 1x1x1 GEMM (R13 structure; epilogue reads fp16 x_s) ----------------
__global__ __launch_bounds__(128) void k_expand(const float* __restrict__ x) {
    __shared__ __align__(16) __half st[CH_][PT];        // 16KB
    __shared__ __align__(16) float swi[2][CH_ * 64];    // 32KB dbl-buffered
    __shared__ float sred[4][64];                       // 1KB

    int tid = threadIdx.x;
    int p0 = blockIdx.x * PT;
    int t = blockIdx.y, b = blockIdx.z;
    int warp = tid >> 5, lane = tid & 31;
    int cog = lane & 7, pxg = lane >> 3;
    int pxb = warp * 32 + pxg * 8;
    bool pv = (p0 + pxb < HW_);

    unsigned st_s = sptr(&st[0][0]);
    unsigned swi_s = sptr(&swi[0][0]);

    const __half* tsrc = (const __half*)g_th + ((size_t)(b * CH_ * T_ + t)) * HW_;
#pragma unroll
    for (int k = 0; k < 8; k++) {
        int q = tid + k * 128;
        int cin = q >> 4, c16 = q & 15;
        if (p0 + c16 * 8 < HW_)
            cpasync16(st_s + q * 16, tsrc + (size_t)cin * T_ * HW_ + p0 + c16 * 8);
        else
            *(uint4*)&st[cin][c16 * 8] = make_uint4(0u, 0u, 0u, 0u);
    }
#pragma unroll
    for (int k = 0; k < 8; k++) {
        int q = tid + k * 128;
        int cin = q >> 4, q16 = q & 15;
        cpasync16(swi_s + q * 16, g_we + cin * 256 + q16 * 4);
    }
    cp_commit();

    for (int chunk = 0; chunk < 4; chunk++) {
        int buf = chunk & 1;
        cp_wait0();
        __syncthreads();

        if (chunk < 3) {
#pragma unroll
            for (int k = 0; k < 8; k++) {
                int q = tid + k * 128;
                int cin = q >> 4, q16 = q & 15;
                cpasync16(swi_s + (buf ^ 1) * 16384 + q * 16,
                          g_we + cin * 256 + (chunk + 1) * 64 + q16 * 4);
            }
            cp_commit();
        }

        ull acc[8][4];
#pragma unroll
        for (int i = 0; i < 8; i++)
#pragma unroll
            for (int j = 0; j < 4; j++) acc[i][j] = 0ULL;

#pragma unroll 4
        for (int cin = 0; cin < CH_; cin++) {
            float4 wlo = *(const float4*)&swi[buf][cin * 64 + cog * 8];
            float4 whi = *(const float4*)&swi[buf][cin * 64 + cog * 8 + 4];
            ull wd[8];
            wd[0] = packdup(wlo.x); wd[1] = packdup(wlo.y);
            wd[2] = packdup(wlo.z); wd[3] = packdup(wlo.w);
            wd[4] = packdup(whi.x); wd[5] = packdup(whi.y);
            wd[6] = packdup(whi.z); wd[7] = packdup(whi.w);
            uint4 hv = *(const uint4*)(const void*)&st[cin][pxb];
            const __half2* hp = (const __half2*)&hv;
            float2 c0 = __half22float2(hp[0]);
            float2 c1 = __half22float2(hp[1]);
            float2 c2 = __half22float2(hp[2]);
            float2 c3 = __half22float2(hp[3]);
            ull xv[4] = {*(ull*)&c0, *(ull*)&c1, *(ull*)&c2, *(ull*)&c3};
#pragma unroll
            for (int i = 0; i < 8; i++)
#pragma unroll
                for (int j = 0; j < 4; j++)
                    ffma2(acc[i][j], wd[i], xv[j]);
        }

        float psum[8];
#pragma unroll
        for (int i = 0; i < 8; i++) {
            psum[i] = 0.f;
            if (pv) {
                int co = chunk * 64 + cog * 8 + i;
                uint4 hv = *(const uint4*)(g_xsh +
                    (((size_t)(b * T_ + t) * C_ + co) * HW_ + p0 + pxb) / 2);
                const __half2* hp = (const __half2*)&hv;
                float2 s0 = __half22float2(hp[0]);
                float2 s1 = __half22float2(hp[1]);
                float2 s2 = __half22float2(hp[2]);
                float2 s3 = __half22float2(hp[3]);
                float2 f0 = unpk(acc[i][0]), f1 = unpk(acc[i][1]);
                float2 f2 = unpk(acc[i][2]), f3 = unpk(acc[i][3]);
                float4 oA, oB;
                oA.x = s0.x * (2.f - 1.f / (1.f + __expf(f0.x)));
                oA.y = s0.y * (2.f - 1.f / (1.f + __expf(f0.y)));
                oA.z = s1.x * (2.f - 1.f / (1.f + __expf(f1.x)));
                oA.w = s1.y * (2.f - 1.f / (1.f + __expf(f1.y)));
                oB.x = s2.x * (2.f - 1.f / (1.f + __expf(f2.x)));
                oB.y = s2.y * (2.f - 1.f / (1.f + __expf(f2.y)));
                oB.z = s3.x * (2.f - 1.f / (1.f + __expf(f3.x)));
                oB.w = s3.y * (2.f - 1.f / (1.f + __expf(f3.y)));
                __half2 h[4];
                h[0] = __floats2half2_rn(oA.x, oA.y);
                h[1] = __floats2half2_rn(oA.z, oA.w);
                h[2] = __floats2half2_rn(oB.x, oB.y);
                h[3] = __floats2half2_rn(oB.z, oB.w);
                *(uint4*)(g_xth + (((size_t)((b * C_ + co) * T_ + t)) * HW_ + p0 + pxb) / 2) =
                    *(const uint4*)h;
                psum[i] = (oA.x + oA.y) + (oA.z + oA.w) + (oB.x + oB.y) + (oB.z + oB.w);
            }
        }
#pragma unroll
        for (int i = 0; i < 8; i++) {
            psum[i] += __shfl_xor_sync(0xffffffffu, psum[i], 8);
            psum[i] += __shfl_xor_sync(0xffffffffu, psum[i], 16);
        }
        if (pxg == 0) {
#pragma unroll
            for (int i = 0; i < 8; i++) sred[warp][cog * 8 + i] = psum[i];
        }
        __syncthreads();
        if (tid < 64) {
            float s = sred[0][tid] + sred[1][tid] + sred[2][tid] + sred[3][tid];
            g_vpart[((size_t)((b * C_ + chunk * 64 + tid) * T_ + t)) * NPB + blockIdx.x] = s;
        }
    }
}

// ---------------- dynamic temporal kernel ----------------
__global__ __launch_bounds__(256) void k_dyn(
    const float* __restrict__ wfc1, const float* __restrict__ bfc1,
    const float* __restrict__ wfc2, const float* __restrict__ bfc2) {
    int id = blockIdx.x * blockDim.x + threadIdx.x;
    if (id >= B_ * C_) return;
    float v[T_];
#pragma unroll
    for (int t = 0; t < T_; t++) {
        const float* pp = g_vpart + ((size_t)id * T_ + t) * NPB;
        float s = 0.f;
#pragma unroll
        for (int k = 0; k < NPB; k++) s += pp[k];
        v[t] = s * (1.f / HW_);
    }
    float lg[3] = {bfc2[0], bfc2[1], bfc2[2]};
#pragma unroll
    for (int hh = 0; hh < 16; hh++) {
        float s = bfc1[hh];
#pragma unroll
        for (int t = 0; t < T_; t++) s += wfc1[hh * 8 + t] * v[t];
        s = fmaxf(s, 0.f);
#pragma unroll
        for (int k = 0; k < 3; k++) lg[k] += wfc2[k * 16 + hh] * s;
    }
    float m = fmaxf(lg[0], fmaxf(lg[1], lg[2]));
    float e0 = __expf(lg[0] - m), e1 = __expf(lg[1] - m), e2 = __expf(lg[2] - m);
    float inv = 1.f / (e0 + e1 + e2);
    g_kern[id * 3 + 0] = e0 * inv;
    g_kern[id * 3 + 1] = e1 * inv;
    g_kern[id * 3 + 2] = e2 * inv;
}

// ---------------- depthwise temporal stencil (fp16 in, fp32 out, 8px/thread) ----------------
__device__ __forceinline__ void cvt8(float* f, uint4 v) {
    __half2 h;
    *(unsigned*)&h = v.x; float2 a = __half22float2(h); f[0] = a.x; f[1] = a.y;
    *(unsigned*)&h = v.y; a = __half22float2(h); f[2] = a.x; f[3] = a.y;
    *(unsigned*)&h = v.z; a = __half22float2(h); f[4] = a.x; f[5] = a.y;
    *(unsigned*)&h = v.w; a = __half22float2(h); f[6] = a.x; f[7] = a.y;
}

__global__ __launch_bounds__(256) void k_stencil(float* __restrict__ out) {
    int p8 = blockIdx.x * blockDim.x + threadIdx.x;
    if (p8 >= HW_ / 8) return;
    int bc = blockIdx.y;
    int b = bc >> 8, c = bc & 255;
    float k0 = g_kern[bc * 3 + 0];
    float k1 = g_kern[bc * 3 + 1];
    float k2 = g_kern[bc * 3 + 2];
    const uint4* src = (const uint4*)(g_xth + (size_t)bc * T_ * (HW_ / 2)) + p8;
    float prev[8], cur[8], nxt[8];
#pragma unroll
    for (int i = 0; i < 8; i++) prev[i] = 0.f;
    cvt8(cur, src[0]);
#pragma unroll
    for (int t = 0; t < T_; t++) {
        if (t < T_ - 1) cvt8(nxt, src[(size_t)(t + 1) * (HW_ / 8)]);
        else {
#pragma unroll
            for (int i = 0; i < 8; i++) nxt[i] = 0.f;
        }
        float* dp = out + ((size_t)((b * T_ + t) * C_ + c)) * HW_ + p8 * 8;
        float4 o1, o2;
        o1.x = k0 * prev[0] + k1 * cur[0] + k2 * nxt[0];
        o1.y = k0 * prev[1] + k1 * cur[1] + k2 * nxt[1];
        o1.z = k0 * prev[2] + k1 * cur[2] + k2 * nxt[2];
        o1.w = k0 * prev[3] + k1 * cur[3] + k2 * nxt[3];
        o2.x = k0 * prev[4] + k1 * cur[4] + k2 * nxt[4];
        o2.y = k0 * prev[5] + k1 * cur[5] + k2 * nxt[5];
        o2.z = k0 * prev[6] + k1 * cur[6] + k2 * nxt[6];
        o2.w = k0 * prev[7] + k1 * cur[7] + k2 * nxt[7];
        *(float4*)dp = o1;
        *(float4*)(dp + 4) = o2;
#pragma unroll
        for (int i = 0; i < 8; i++) { prev[i] = cur[i]; cur[i] = nxt[i]; }
    }
}

// ---------------- launch ----------------
extern "C" void kernel_launch(void* const* d_in, const int* in_sizes, int n_in,
                              void* d_out, int out_size) {
    const float* x      = (const float*)d_in[0];
    const float* w_sp   = (const float*)d_in[1];
    const float* w_red  = (const float*)d_in[2];
    const float* gam    = (const float*)d_in[3];
    const float* bet    = (const float*)d_in[4];
    const float* mea    = (const float*)d_in[5];
    const float* var    = (const float*)d_in[6];
    const float* w_exp  = (const float*)d_in[7];
    const float* wfc1   = (const float*)d_in[8];
    const float* bfc1   = (const float*)d_in[9];
    const float* wfc2   = (const float*)d_in[10];
    const float* bfc2   = (const float*)d_in[11];
    float* out = (float*)d_out;

    k_prep<<<192, 256>>>(w_red, w_exp);
    k_maxmean<<<dim3(4, B_ * T_), 256>>>(x);
    k_spatial<<<dim3(13, B_ * T_), 256>>>(w_sp);
    k_reduce<<<dim3(HW_ / PXT, B_), 128>>>(x, gam, bet, mea, var);
    k_expand<<<dim3(NPB, T_, B_), 128>>>(x);
    k_dyn<<<8, 256>>>(wfc1, bfc1, wfc2, bfc2);
    k_stencil<<<dim3(2, B_ * C_), 256>>>(out);
}

// round 17
// speedup vs baseline: 1.0161x; 1.0161x over previous
#include <cuda_runtime.h>
#include <cuda_fp16.h>
#include <math.h>
#include <stdint.h>

#define B_    8
#define T_    8
#define C_    256
#define CH_   64
#define Wd    56
#define HW_   3136
#define PT    128
#define NPB   25          // expand px-blocks / v-partial slots
#define PXT   16          // px per block in k_reduce

typedef unsigned long long ull;

// ---------------- scratch (device globals) ----------------
__device__ float g_maxavg[(size_t)B_ * T_ * 2 * HW_];
__device__ float g_gate[(size_t)B_ * T_ * HW_];
__device__ __align__(16) float g_wrf[C_ * 3 * CH_];     // [c*192 + dt*64 + ch]
__device__ __align__(16) float g_we[CH_ * C_];          // [cin*256 + cout]
__device__ __align__(16) __half2 g_th[(size_t)B_ * CH_ * T_ * HW_ / 2];   // fp16 t-buffer
__device__ __align__(16) __half2 g_xsh[(size_t)B_ * T_ * C_ * HW_ / 2];   // fp16 x_s = x*gate
__device__ __align__(16) __half2 g_xth[(size_t)B_ * C_ * T_ * HW_ / 2];   // fp16 x_t
__device__ float g_vpart[(size_t)B_ * C_ * T_ * NPB];
__device__ float g_kern[B_ * C_ * 3];

// ---------------- helpers ----------------
__device__ __forceinline__ void ffma2(ull& d, ull a, ull b) {
    asm("fma.rn.f32x2 %0, %1, %2, %0;" : "+l"(d) : "l"(a), "l"(b));
}
__device__ __forceinline__ ull packdup(float w) {
    ull u; asm("mov.b64 %0, {%1, %1};" : "=l"(u) : "f"(w)); return u;
}
__device__ __forceinline__ float2 unpk(ull u) {
    float2 f; asm("mov.b64 {%0, %1}, %2;" : "=f"(f.x), "=f"(f.y) : "l"(u)); return f;
}
__device__ __forceinline__ unsigned sptr(const void* p) {
    return (unsigned)__cvta_generic_to_shared(p);
}
__device__ __forceinline__ void cpasync16(unsigned dst, const void* src) {
    asm volatile("cp.async.ca.shared.global [%0], [%1], 16;" :: "r"(dst), "l"(src));
}
__device__ __forceinline__ void cp_commit() { asm volatile("cp.async.commit_group;"); }
__device__ __forceinline__ void cp_wait0()  { asm volatile("cp.async.wait_group 0;"); }

// ---------------- prep: weight transposes ----------------
__global__ void k_prep(const float* __restrict__ wr, const float* __restrict__ we) {
    int idx = blockIdx.x * blockDim.x + threadIdx.x;
    if (idx < C_ * 3 * CH_) {
        int c = idx / 192;
        int r = idx % 192;
        int dt = r / 64, ch = r % 64;
        g_wrf[idx] = wr[ch * (C_ * 3) + c * 3 + dt];
    }
    if (idx < CH_ * C_) {
        int cout = idx & 255, cin = idx >> 8;
        g_we[idx] = we[cout * CH_ + cin];
    }
}

// ---------------- channel max/mean (float4) ----------------
__global__ __launch_bounds__(256) void k_maxmean(const float* __restrict__ x) {
    int bt = blockIdx.y;
    int p4 = blockIdx.x * blockDim.x + threadIdx.x;
    if (p4 >= HW_ / 4) return;
    const float4* xp = (const float4*)(x + (size_t)bt * C_ * HW_) + p4;
    float4 mx = xp[0];
    float4 sm = mx;
#pragma unroll 4
    for (int c = 1; c < C_; c++) {
        float4 v = xp[(size_t)c * (HW_ / 4)];
        mx.x = fmaxf(mx.x, v.x); mx.y = fmaxf(mx.y, v.y);
        mx.z = fmaxf(mx.z, v.z); mx.w = fmaxf(mx.w, v.w);
        sm.x += v.x; sm.y += v.y; sm.z += v.z; sm.w += v.w;
    }
    float4* mo = (float4*)(g_maxavg + (size_t)bt * 2 * HW_);
    mo[p4] = mx;
    sm.x *= (1.f / C_); sm.y *= (1.f / C_); sm.z *= (1.f / C_); sm.w *= (1.f / C_);
    mo[HW_ / 4 + p4] = sm;
}

// ---------------- 7x7 conv -> spatial gate ----------------
__global__ __launch_bounds__(256) void k_spatial(const float* __restrict__ w) {
    __shared__ float sw[98];
    int tid = threadIdx.x;
    if (tid < 98) sw[tid] = w[tid];
    __syncthreads();
    int bt = blockIdx.y;
    int p = blockIdx.x * blockDim.x + tid;
    if (p >= HW_) return;
    int py = p / Wd, px = p % Wd;
    const float* mb = g_maxavg + (size_t)bt * 2 * HW_;
    float s = 0.f;
#pragma unroll
    for (int ky = 0; ky < 7; ky++) {
        int iy = py + ky - 3;
        if (iy < 0 || iy >= Wd) continue;
#pragma unroll
        for (int kx = 0; kx < 7; kx++) {
            int ix = px + kx - 3;
            if (ix < 0 || ix >= Wd) continue;
            float m = mb[iy * Wd + ix];
            float a = mb[HW_ + iy * Wd + ix];
            s += sw[ky * 7 + kx] * m + sw[49 + ky * 7 + kx] * a;
        }
    }
    g_gate[(size_t)bt * HW_ + p] = 1.f + 1.f / (1.f + __expf(-s));
}

// ---------------- t-batched gated reduce conv3d + BN + relu (R13 body + reg-lean x_s export) ----------------
__global__ __launch_bounds__(128) void k_reduce(
    const float* __restrict__ x, const float* __restrict__ gamma,
    const float* __restrict__ beta, const float* __restrict__ mean,
    const float* __restrict__ var) {
    __shared__ float sinv[64], sbias[64];
    __shared__ __align__(16) ull sg[8][8];
    __shared__ __align__(16) ull sxs[8][8][10];
    __shared__ __align__(16) float swf[2][1536];

    int tid = threadIdx.x;
    int warp = tid >> 5, lane = tid & 31;
    int chg = lane & 15, pxg = lane >> 4;
    int pair = warp * 2 + pxg;
    int p0 = blockIdx.x * PXT;
    int b = blockIdx.y;

    if (tid < 64) {
        float iv = gamma[tid] * rsqrtf(var[tid] + 1e-5f);
        sinv[tid] = iv;
        sbias[tid] = beta[tid] - mean[tid] * iv;
        int tin = tid >> 3, pr = tid & 7;
        float2 g = *(const float2*)(g_gate + (size_t)(b * T_ + tin) * HW_ + p0 + pr * 2);
        sg[tin][pr] = *(ull*)&g;
    }
    {
        int c = tid >> 3, pr = tid & 7;
        if (c < 8) {
            sxs[c][pr][0] = 0ULL;
            sxs[c][pr][9] = 0ULL;
        }
    }
    __syncthreads();

    int sc = tid >> 4, sp = tid & 7, shalf = (tid >> 3) & 1;
    const float* xb = x + ((size_t)b * T_ * C_) * HW_ + p0 + sp * 2;
    float2 sgate[4];
#pragma unroll
    for (int k = 0; k < 4; k++) {
        ull g = sg[shalf * 4 + k][sp];
        sgate[k] = unpk(g);
    }

    // SINGLE export pointer (k-offsets are compile-time constants: tin stride = C_*HW_/2 half2)
    __half2* xsh_p = g_xsh + (((size_t)(b * T_ + shalf * 4) * C_ + sc) * HW_ + p0 + sp * 2) / 2;

    unsigned swf_s = sptr(&swf[0][0]);

#pragma unroll
    for (int k = 0; k < 3; k++) {
        int q = tid + k * 128;
        cpasync16(swf_s + q * 16, g_wrf + q * 4);
    }
    cp_commit();
    float2 xf[4];
#pragma unroll
    for (int k = 0; k < 4; k++) {
        int tin = shalf * 4 + k;
        xf[k] = *(const float2*)(xb + ((size_t)(tin * C_ + sc)) * HW_);
    }

    ull acc[4][8];
#pragma unroll
    for (int i = 0; i < 4; i++)
#pragma unroll
        for (int t = 0; t < 8; t++) acc[i][t] = 0ULL;

    for (int c0 = 0; c0 < C_; c0 += 8) {
        int buf = (c0 >> 3) & 1;
        __syncthreads();
#pragma unroll
        for (int k = 0; k < 4; k++) {
            float2 v;
            v.x = xf[k].x * sgate[k].x;
            v.y = xf[k].y * sgate[k].y;
            sxs[sc][sp][1 + shalf * 4 + k] = *(ull*)&v;
            xsh_p[(size_t)k * (C_ * HW_ / 2)] = __floats2half2_rn(v.x, v.y);
        }
        xsh_p += 4 * HW_;                       // c += 8
        cp_wait0();
        __syncthreads();

        if (c0 + 8 < C_) {
#pragma unroll
            for (int k = 0; k < 3; k++) {
                int q = tid + k * 128;
                cpasync16(swf_s + (buf ^ 1) * 6144 + q * 16,
                          g_wrf + (c0 + 8) * 192 + q * 4);
            }
            cp_commit();
#pragma unroll
            for (int k = 0; k < 4; k++) {
                int tin = shalf * 4 + k;
                xf[k] = *(const float2*)(xb + ((size_t)(tin * C_ + c0 + 8 + sc)) * HW_);
            }
        }

#pragma unroll 2
        for (int cc = 0; cc < 8; cc++) {
            const ulonglong2* xp2 = (const ulonglong2*)&sxs[cc][pair][0];
            ulonglong2 a0 = xp2[0], a1 = xp2[1], a2 = xp2[2], a3 = xp2[3], a4 = xp2[4];
            ull xv[10] = {a0.x, a0.y, a1.x, a1.y, a2.x, a2.y, a3.x, a3.y, a4.x, a4.y};
#pragma unroll
            for (int dt = 0; dt < 3; dt++) {
                float4 wq = *(const float4*)&swf[buf][cc * 192 + dt * 64 + chg * 4];
                ull w0 = packdup(wq.x), w1 = packdup(wq.y);
                ull w2 = packdup(wq.z), w3 = packdup(wq.w);
#pragma unroll
                for (int t = 0; t < 8; t++) {
                    ffma2(acc[0][t], w0, xv[t + dt]);
                    ffma2(acc[1][t], w1, xv[t + dt]);
                    ffma2(acc[2][t], w2, xv[t + dt]);
                    ffma2(acc[3][t], w3, xv[t + dt]);
                }
            }
        }
    }

    int px = p0 + pair * 2;
#pragma unroll
    for (int i = 0; i < 4; i++) {
        int ch = chg * 4 + i;
        float inv = sinv[ch], bia = sbias[ch];
        __half2* dst = g_th + ((((size_t)(b * CH_ + ch)) * T_) * HW_ + px) / 2;
#pragma unroll
        for (int t = 0; t < 8; t++) {
            float2 f = unpk(acc[i][t]);
            float ox = fmaxf(fmaf(f.x, inv, bia), 0.f);
            float oy = fmaxf(fmaf(f.y, inv, bia), 0.f);
            dst[(size_t)t * (HW_ / 2)] = __floats2half2_rn(ox, oy);
        }
    }
}

// ---------------- expand 1x1x1 GEMM (R13 structure; epilogue reads fp16 x_s) ----------------
__global__ __launch_bounds__(128) void k_expand() {
    __shared__ __align__(16) __half st[CH_][PT];        // 16KB
    __shared__ __align__(16) float swi[2][CH_ * 64];    // 32KB dbl-buffered
    __shared__ float sred[4][64];                       // 1KB

    int tid = threadIdx.x;
    int p0 = blockIdx.x * PT;
    int t = blockIdx.y, b = blockIdx.z;
    int warp = tid >> 5, lane = tid & 31;
    int cog = lane & 7, pxg = lane >> 3;
    int pxb = warp * 32 + pxg * 8;
    bool pv = (p0 + pxb < HW_);

    unsigned st_s = sptr(&st[0][0]);
    unsigned swi_s = sptr(&swi[0][0]);

    const __half* tsrc = (const __half*)g_th + ((size_t)(b * CH_ * T_ + t)) * HW_;
#pragma unroll
    for (int k = 0; k < 8; k++) {
        int q = tid + k * 128;
        int cin = q >> 4, c16 = q & 15;
        if (p0 + c16 * 8 < HW_)
            cpasync16(st_s + q * 16, tsrc + (size_t)cin * T_ * HW_ + p0 + c16 * 8);
        else
            *(uint4*)&st[cin][c16 * 8] = make_uint4(0u, 0u, 0u, 0u);
    }
#pragma unroll
    for (int k = 0; k < 8; k++) {
        int q = tid + k * 128;
        int cin = q >> 4, q16 = q & 15;
        cpasync16(swi_s + q * 16, g_we + cin * 256 + q16 * 4);
    }
    cp_commit();

    for (int chunk = 0; chunk < 4; chunk++) {
        int buf = chunk & 1;
        cp_wait0();
        __syncthreads();

        if (chunk < 3) {
#pragma unroll
            for (int k = 0; k < 8; k++) {
                int q = tid + k * 128;
                int cin = q >> 4, q16 = q & 15;
                cpasync16(swi_s + (buf ^ 1) * 16384 + q * 16,
                          g_we + cin * 256 + (chunk + 1) * 64 + q16 * 4);
            }
            cp_commit();
        }

        ull acc[8][4];
#pragma unroll
        for (int i = 0; i < 8; i++)
#pragma unroll
            for (int j = 0; j < 4; j++) acc[i][j] = 0ULL;

#pragma unroll 4
        for (int cin = 0; cin < CH_; cin++) {
            float4 wlo = *(const float4*)&swi[buf][cin * 64 + cog * 8];
            float4 whi = *(const float4*)&swi[buf][cin * 64 + cog * 8 + 4];
            ull wd[8];
            wd[0] = packdup(wlo.x); wd[1] = packdup(wlo.y);
            wd[2] = packdup(wlo.z); wd[3] = packdup(wlo.w);
            wd[4] = packdup(whi.x); wd[5] = packdup(whi.y);
            wd[6] = packdup(whi.z); wd[7] = packdup(whi.w);
            uint4 hv = *(const uint4*)(const void*)&st[cin][pxb];
            const __half2* hp = (const __half2*)&hv;
            float2 c0 = __half22float2(hp[0]);
            float2 c1 = __half22float2(hp[1]);
            float2 c2 = __half22float2(hp[2]);
            float2 c3 = __half22float2(hp[3]);
            ull xv[4] = {*(ull*)&c0, *(ull*)&c1, *(ull*)&c2, *(ull*)&c3};
#pragma unroll
            for (int i = 0; i < 8; i++)
#pragma unroll
                for (int j = 0; j < 4; j++)
                    ffma2(acc[i][j], wd[i], xv[j]);
        }

        float psum[8];
#pragma unroll
        for (int i = 0; i < 8; i++) {
            psum[i] = 0.f;
            if (pv) {
                int co = chunk * 64 + cog * 8 + i;
                uint4 hv = *(const uint4*)(g_xsh +
                    (((size_t)(b * T_ + t) * C_ + co) * HW_ + p0 + pxb) / 2);
                const __half2* hp = (const __half2*)&hv;
                float2 s0 = __half22float2(hp[0]);
                float2 s1 = __half22float2(hp[1]);
                float2 s2 = __half22float2(hp[2]);
                float2 s3 = __half22float2(hp[3]);
                float2 f0 = unpk(acc[i][0]), f1 = unpk(acc[i][1]);
                float2 f2 = unpk(acc[i][2]), f3 = unpk(acc[i][3]);
                float4 oA, oB;
                oA.x = s0.x * (2.f - 1.f / (1.f + __expf(f0.x)));
                oA.y = s0.y * (2.f - 1.f / (1.f + __expf(f0.y)));
                oA.z = s1.x * (2.f - 1.f / (1.f + __expf(f1.x)));
                oA.w = s1.y * (2.f - 1.f / (1.f + __expf(f1.y)));
                oB.x = s2.x * (2.f - 1.f / (1.f + __expf(f2.x)));
                oB.y = s2.y * (2.f - 1.f / (1.f + __expf(f2.y)));
                oB.z = s3.x * (2.f - 1.f / (1.f + __expf(f3.x)));
                oB.w = s3.y * (2.f - 1.f / (1.f + __expf(f3.y)));
                __half2 h[4];
                h[0] = __floats2half2_rn(oA.x, oA.y);
                h[1] = __floats2half2_rn(oA.z, oA.w);
                h[2] = __floats2half2_rn(oB.x, oB.y);
                h[3] = __floats2half2_rn(oB.z, oB.w);
                *(uint4*)(g_xth + (((size_t)((b * C_ + co) * T_ + t)) * HW_ + p0 + pxb) / 2) =
                    *(const uint4*)h;
                psum[i] = (oA.x + oA.y) + (oA.z + oA.w) + (oB.x + oB.y) + (oB.z + oB.w);
            }
        }
#pragma unroll
        for (int i = 0; i < 8; i++) {
            psum[i] += __shfl_xor_sync(0xffffffffu, psum[i], 8);
            psum[i] += __shfl_xor_sync(0xffffffffu, psum[i], 16);
        }
        if (pxg == 0) {
#pragma unroll
            for (int i = 0; i < 8; i++) sred[warp][cog * 8 + i] = psum[i];
        }
        __syncthreads();
        if (tid < 64) {
            float s = sred[0][tid] + sred[1][tid] + sred[2][tid] + sred[3][tid];
            g_vpart[((size_t)((b * C_ + chunk * 64 + tid) * T_ + t)) * NPB + blockIdx.x] = s;
        }
    }
}

// ---------------- dynamic temporal kernel ----------------
__global__ __launch_bounds__(256) void k_dyn(
    const float* __restrict__ wfc1, const float* __restrict__ bfc1,
    const float* __restrict__ wfc2, const float* __restrict__ bfc2) {
    int id = blockIdx.x * blockDim.x + threadIdx.x;
    if (id >= B_ * C_) return;
    float v[T_];
#pragma unroll
    for (int t = 0; t < T_; t++) {
        const float* pp = g_vpart + ((size_t)id * T_ + t) * NPB;
        float s = 0.f;
#pragma unroll
        for (int k = 0; k < NPB; k++) s += pp[k];
        v[t] = s * (1.f / HW_);
    }
    float lg[3] = {bfc2[0], bfc2[1], bfc2[2]};
#pragma unroll
    for (int hh = 0; hh < 16; hh++) {
        float s = bfc1[hh];
#pragma unroll
        for (int t = 0; t < T_; t++) s += wfc1[hh * 8 + t] * v[t];
        s = fmaxf(s, 0.f);
#pragma unroll
        for (int k = 0; k < 3; k++) lg[k] += wfc2[k * 16 + hh] * s;
    }
    float m = fmaxf(lg[0], fmaxf(lg[1], lg[2]));
    float e0 = __expf(lg[0] - m), e1 = __expf(lg[1] - m), e2 = __expf(lg[2] - m);
    float inv = 1.f / (e0 + e1 + e2);
    g_kern[id * 3 + 0] = e0 * inv;
    g_kern[id * 3 + 1] = e1 * inv;
    g_kern[id * 3 + 2] = e2 * inv;
}

// ---------------- depthwise temporal stencil (fp16 in, fp32 out, 8px/thread) ----------------
__device__ __forceinline__ void cvt8(float* f, uint4 v) {
    __half2 h;
    *(unsigned*)&h = v.x; float2 a = __half22float2(h); f[0] = a.x; f[1] = a.y;
    *(unsigned*)&h = v.y; a = __half22float2(h); f[2] = a.x; f[3] = a.y;
    *(unsigned*)&h = v.z; a = __half22float2(h); f[4] = a.x; f[5] = a.y;
    *(unsigned*)&h = v.w; a = __half22float2(h); f[6] = a.x; f[7] = a.y;
}

__global__ __launch_bounds__(256) void k_stencil(float* __restrict__ out) {
    int p8 = blockIdx.x * blockDim.x + threadIdx.x;
    if (p8 >= HW_ / 8) return;
    int bc = blockIdx.y;
    int b = bc >> 8, c = bc & 255;
    float k0 = g_kern[bc * 3 + 0];
    float k1 = g_kern[bc * 3 + 1];
    float k2 = g_kern[bc * 3 + 2];
    const uint4* src = (const uint4*)(g_xth + (size_t)bc * T_ * (HW_ / 2)) + p8;
    float prev[8], cur[8], nxt[8];
#pragma unroll
    for (int i = 0; i < 8; i++) prev[i] = 0.f;
    cvt8(cur, src[0]);
#pragma unroll
    for (int t = 0; t < T_; t++) {
        if (t < T_ - 1) cvt8(nxt, src[(size_t)(t + 1) * (HW_ / 8)]);
        else {
#pragma unroll
            for (int i = 0; i < 8; i++) nxt[i] = 0.f;
        }
        float* dp = out + ((size_t)((b * T_ + t) * C_ + c)) * HW_ + p8 * 8;
        float4 o1, o2;
        o1.x = k0 * prev[0] + k1 * cur[0] + k2 * nxt[0];
        o1.y = k0 * prev[1] + k1 * cur[1] + k2 * nxt[1];
        o1.z = k0 * prev[2] + k1 * cur[2] + k2 * nxt[2];
        o1.w = k0 * prev[3] + k1 * cur[3] + k2 * nxt[3];
        o2.x = k0 * prev[4] + k1 * cur[4] + k2 * nxt[4];
        o2.y = k0 * prev[5] + k1 * cur[5] + k2 * nxt[5];
        o2.z = k0 * prev[6] + k1 * cur[6] + k2 * nxt[6];
        o2.w = k0 * prev[7] + k1 * cur[7] + k2 * nxt[7];
        *(float4*)dp = o1;
        *(float4*)(dp + 4) = o2;
#pragma unroll
        for (int i = 0; i < 8; i++) { prev[i] = cur[i]; cur[i] = nxt[i]; }
    }
}

// ---------------- launch ----------------
extern "C" void kernel_launch(void* const* d_in, const int* in_sizes, int n_in,
                              void* d_out, int out_size) {
    const float* x      = (const float*)d_in[0];
    const float* w_sp   = (const float*)d_in[1];
    const float* w_red  = (const float*)d_in[2];
    const float* gam    = (const float*)d_in[3];
    const float* bet    = (const float*)d_in[4];
    const float* mea    = (const float*)d_in[5];
    const float* var    = (const float*)d_in[6];
    const float* w_exp  = (const float*)d_in[7];
    const float* wfc1   = (const float*)d_in[8];
    const float* bfc1   = (const float*)d_in[9];
    const float* wfc2   = (const float*)d_in[10];
    const float* bfc2   = (const float*)d_in[11];
    float* out = (float*)d_out;

    k_prep<<<192, 256>>>(w_red, w_exp);
    k_maxmean<<<dim3(4, B_ * T_), 256>>>(x);
    k_spatial<<<dim3(13, B_ * T_), 256>>>(w_sp);
    k_reduce<<<dim3(HW_ / PXT, B_), 128>>>(x, gam, bet, mea, var);
    k_expand<<<dim3(NPB, T_, B_), 128>>>();
    k_dyn<<<8, 256>>>(wfc1, bfc1, wfc2, bfc2);
    k_stencil<<<dim3(2, B_ * C_), 256>>>(out);
}